// round 7
// baseline (speedup 1.0000x reference)
#include <cuda_runtime.h>
#include <cuda_fp16.h>
#include <cstdint>

#define EPSV 1e-5f

// ---------------- scratch (device globals; no allocation allowed) ----------------
__device__ float g_p2[8ull * 128 * 64 * 64];     // pooled stage 2: (B,C,64,64)
__device__ float g_part[8ull * 32 * 128 * 128];  // gram partials: (B, 32 splits, C, C)
__device__ float g_St[8ull * 128 * 128];         // sim transposed: [b][c][k]

// ============ kernel 1: fused (dwconv s2 + BN + PReLU) x2 : x -> p2 directly ============
// grid (4 row-tiles, 1024 bc), 256 threads. Per block: p2 rows [tile*16, tile*16+16) x 64.
// Needs p1 rows 2r0-1 .. 2r0+31 (33), x rows 4r0-3 .. 4r0+63 (67).
#define XS_ROWS 67
#define P1_ROWS 33

__global__ __launch_bounds__(256) void fused_pool_kernel(
    const float* __restrict__ x,
    const float* __restrict__ w1,
    const float* __restrict__ g1, const float* __restrict__ be1,
    const float* __restrict__ m1, const float* __restrict__ v1,
    const float* __restrict__ a1,
    const float* __restrict__ w2,
    const float* __restrict__ g2, const float* __restrict__ be2,
    const float* __restrict__ m2, const float* __restrict__ v2,
    const float* __restrict__ a2)
{
    extern __shared__ float sm[];
    float* Xs = sm;                       // [67][256]
    float* P1 = sm + XS_ROWS * 256;       // [33][128]

    int bc   = blockIdx.y;                // b*128 + c
    int c    = bc & 127;
    int r0   = blockIdx.x * 16;           // p2 row base
    int tid  = threadIdx.x;

    const float* xp = x + (size_t)bc * 65536;

    float wa0 = w1[c*9+0], wa1 = w1[c*9+1], wa2 = w1[c*9+2];
    float wa3 = w1[c*9+3], wa4 = w1[c*9+4], wa5 = w1[c*9+5];
    float wa6 = w1[c*9+6], wa7 = w1[c*9+7], wa8 = w1[c*9+8];
    float inv1  = g1[c] * rsqrtf(v1[c] + EPSV);
    float bias1 = be1[c] - m1[c] * inv1;
    float al1   = a1[c];

    float ub0 = w2[c*9+0], ub1 = w2[c*9+1], ub2 = w2[c*9+2];
    float ub3 = w2[c*9+3], ub4 = w2[c*9+4], ub5 = w2[c*9+5];
    float ub6 = w2[c*9+6], ub7 = w2[c*9+7], ub8 = w2[c*9+8];
    float inv2  = g2[c] * rsqrtf(v2[c] + EPSV);
    float bias2 = be2[c] - m2[c] * inv2;
    float al2   = a2[c];

    // ---- fill Xs (zero rows outside [0,255])
    int iy_base = 4 * r0 - 3;
    for (int idx = tid; idx < XS_ROWS * 64; idx += 256) {
        int r = idx >> 6, c4 = (idx & 63) * 4;
        int iy = iy_base + r;
        float4 v = make_float4(0.f, 0.f, 0.f, 0.f);
        if (iy >= 0 && iy < 256)
            v = *(const float4*)(xp + (size_t)iy * 256 + c4);
        *(float4*)(Xs + r * 256 + c4) = v;
    }
    __syncthreads();

    // ---- p1: py in [2r0-1, 2r0+31] (local rows map so Xs row = 2*r)
    for (int idx = tid; idx < P1_ROWS * 128; idx += 256) {
        int r = idx >> 7, px = idx & 127;
        int py = (2 * r0 - 1) + r;
        float out = 0.f;
        if (py >= 0 && py < 128) {
            int ix0 = 2 * px - 1;
            bool L = (ix0 >= 0);
            const float* x0 = Xs + (2 * r) * 256;
            const float* x1 = x0 + 256;
            const float* x2 = x1 + 256;
            float s = 0.f;
            if (L) s += wa0 * x0[ix0];
            s += wa1 * x0[ix0 + 1];
            s += wa2 * x0[ix0 + 2];
            if (L) s += wa3 * x1[ix0];
            s += wa4 * x1[ix0 + 1];
            s += wa5 * x1[ix0 + 2];
            if (L) s += wa6 * x2[ix0];
            s += wa7 * x2[ix0 + 1];
            s += wa8 * x2[ix0 + 2];
            float y = s * inv1 + bias1;
            out = (y > 0.f) ? y : al1 * y;
        }
        P1[r * 128 + px] = out;
    }
    __syncthreads();

    // ---- p2: 16 x 64 (P1 local row = 2*qr for py=2qy-1)
    float* op = g_p2 + (size_t)bc * 4096;
    for (int idx = tid; idx < 1024; idx += 256) {
        int qr = idx >> 6, qx = idx & 63;
        int jx0 = 2 * qx - 1;
        bool L = (jx0 >= 0);
        const float* p0 = P1 + (2 * qr) * 128;
        const float* p1r = p0 + 128;
        const float* p2r = p1r + 128;
        float s = 0.f;
        if (L) s += ub0 * p0[jx0];
        s += ub1 * p0[jx0 + 1];
        s += ub2 * p0[jx0 + 2];
        if (L) s += ub3 * p1r[jx0];
        s += ub4 * p1r[jx0 + 1];
        s += ub5 * p1r[jx0 + 2];
        if (L) s += ub6 * p2r[jx0];
        s += ub7 * p2r[jx0 + 1];
        s += ub8 * p2r[jx0 + 2];
        float y = s * inv2 + bias2;
        op[(size_t)(r0 + qr) * 64 + qx] = (y > 0.f) ? y : al2 * y;
    }
}

// ---------------- kernel 3: gram partials ----------------
__global__ __launch_bounds__(256) void gram_partial_kernel()
{
    extern __shared__ float P[];       // [128 n][128 c]
    int s = blockIdx.x, b = blockIdx.y;
    int tid = threadIdx.x;

    const float* src = g_p2 + (size_t)b * 128 * 4096 + (size_t)s * 128;
    for (int idx = tid; idx < 4096; idx += 256) {
        int c = idx & 127, ng = idx >> 7;
        float4 v = *(const float4*)(src + (size_t)c * 4096 + ng * 4);
        P[(ng * 4 + 0) * 128 + c] = v.x;
        P[(ng * 4 + 1) * 128 + c] = v.y;
        P[(ng * 4 + 2) * 128 + c] = v.z;
        P[(ng * 4 + 3) * 128 + c] = v.w;
    }
    __syncthreads();

    int i0 = (tid >> 4) * 8;
    int j0 = (tid & 15) * 8;
    float acc[8][8];
#pragma unroll
    for (int ii = 0; ii < 8; ++ii)
#pragma unroll
        for (int jj = 0; jj < 8; ++jj) acc[ii][jj] = 0.f;

    for (int n = 0; n < 128; ++n) {
        const float* row = P + n * 128;
        float4 a0 = *(const float4*)(row + i0);
        float4 a1 = *(const float4*)(row + i0 + 4);
        float4 b0 = *(const float4*)(row + j0);
        float4 b1 = *(const float4*)(row + j0 + 4);
        float ai[8] = {a0.x, a0.y, a0.z, a0.w, a1.x, a1.y, a1.z, a1.w};
        float bj[8] = {b0.x, b0.y, b0.z, b0.w, b1.x, b1.y, b1.z, b1.w};
#pragma unroll
        for (int ii = 0; ii < 8; ++ii)
#pragma unroll
            for (int jj = 0; jj < 8; ++jj)
                acc[ii][jj] = fmaf(ai[ii], bj[jj], acc[ii][jj]);
    }

    float* dst = g_part + ((size_t)b * 32 + s) * 16384;
#pragma unroll
    for (int ii = 0; ii < 8; ++ii) {
        float4 v0 = make_float4(acc[ii][0], acc[ii][1], acc[ii][2], acc[ii][3]);
        float4 v1 = make_float4(acc[ii][4], acc[ii][5], acc[ii][6], acc[ii][7]);
        float* op = dst + (size_t)(i0 + ii) * 128 + j0;
        *(float4*)op = v0;
        *(float4*)(op + 4) = v1;
    }
}

// ---------------- kernel 4: reduce, scale, softmax; store TRANSPOSED sim ----
__global__ void softmax_kernel()
{
    int i = blockIdx.x, b = blockIdx.y, j = threadIdx.x;   // i = row k, j = col c
    const float* p = g_part + (size_t)b * 32 * 16384 + (size_t)i * 128 + j;
    float g = 0.f;
#pragma unroll
    for (int s = 0; s < 32; ++s) g += p[(size_t)s * 16384];
    g *= (1.0f / 64.0f);   // (64*64)^-0.5

    __shared__ float buf[128];
    buf[j] = g;
    __syncthreads();
    for (int off = 64; off > 0; off >>= 1) {
        if (j < off) buf[j] = fmaxf(buf[j], buf[j + off]);
        __syncthreads();
    }
    float m = buf[0];
    __syncthreads();
    float e = __expf(g - m);
    buf[j] = e;
    __syncthreads();
    for (int off = 64; off > 0; off >>= 1) {
        if (j < off) buf[j] = buf[j] + buf[j + off];
        __syncthreads();
    }
    float r = e / buf[0];
    g_St[(size_t)b * 16384 + (size_t)j * 128 + i] = r;   // [b][c][k]
}

// ---------------- kernel 5: out[b,c,n] = sum_k sim[b,k,c]*x[b,k,n], fp16 single-product MMA ----
#define LDA 136
#define LDB 136
#define NT  4   // n-tiles (128 wide) per block

__device__ __forceinline__ unsigned smem_u32(const void* p) {
    return (unsigned)__cvta_generic_to_shared(p);
}

#define LDSM_X4(r, addr) \
    asm volatile("ldmatrix.sync.aligned.m8n8.x4.shared.b16 {%0,%1,%2,%3},[%4];" \
        : "=r"((r)[0]), "=r"((r)[1]), "=r"((r)[2]), "=r"((r)[3]) : "r"(addr))

#define LDSM_X4_T(r, addr) \
    asm volatile("ldmatrix.sync.aligned.m8n8.x4.trans.shared.b16 {%0,%1,%2,%3},[%4];" \
        : "=r"((r)[0]), "=r"((r)[1]), "=r"((r)[2]), "=r"((r)[3]) : "r"(addr))

#define MMAF16(C, A, b0, b1) \
    asm volatile("mma.sync.aligned.m16n8k16.row.col.f32.f16.f16.f32 " \
        "{%0,%1,%2,%3},{%4,%5,%6,%7},{%8,%9},{%0,%1,%2,%3};" \
        : "+f"((C)[0]), "+f"((C)[1]), "+f"((C)[2]), "+f"((C)[3]) \
        : "r"((A)[0]), "r"((A)[1]), "r"((A)[2]), "r"((A)[3]), "r"(b0), "r"(b1))

#define CP_ASYNC16(dst, src) \
    asm volatile("cp.async.cg.shared.global [%0],[%1],16;" :: "r"(dst), "l"(src))
#define CP_COMMIT() asm volatile("cp.async.commit_group;")
#define CP_WAIT0()  asm volatile("cp.async.wait_group 0;" ::: "memory")

__global__ __launch_bounds__(256) void attn_mma_kernel(const float* __restrict__ x,
                                                       float* __restrict__ out)
{
    extern __shared__ char smraw[];
    __half* Ahi = (__half*)smraw;              // [128 c][LDA k]
    __half* B0  = Ahi + 128 * LDA;             // [128 k][LDB n], double buffered
    __half* B1  = B0 + 128 * LDB;
    float*  Xs  = (float*)(B1 + 128 * LDB);    // staging [128 k][128 n] fp32

    int b    = blockIdx.y;
    int tid  = threadIdx.x;
    int warp = tid >> 5, lane = tid & 31;

    const float* xb = x + (size_t)b * 128 * 65536;
    float*       ob = out + (size_t)b * 128 * 65536;

    // ---- prefetch tile 0 via cp.async (each thread owns a fixed Xs region)
    {
        int n0 = blockIdx.x * NT * 128;
#pragma unroll
        for (int i = 0; i < 16; ++i) {
            int idx = i * 256 + tid;
            int k = idx >> 5, c4 = idx & 31;
            CP_ASYNC16(smem_u32(Xs + k * 128 + c4 * 4),
                       xb + (size_t)k * 65536 + n0 + c4 * 4);
        }
        CP_COMMIT();
    }

    // ---- A prep: g_St[b] ([c][k] fp32) -> fp16
    {
        const float* Sp = g_St + (size_t)b * 16384;
#pragma unroll
        for (int i = 0; i < 16; ++i) {
            int idx = i * 256 + tid;
            int c = idx >> 5, k4 = (idx & 31) * 4;
            float4 v = *(const float4*)(Sp + c * 128 + k4);
            __half* ph = Ahi + c * LDA + k4;
            *(__half2*)(ph)     = __floats2half2_rn(v.x, v.y);
            *(__half2*)(ph + 2) = __floats2half2_rn(v.z, v.w);
        }
    }

    int mw = (warp >> 1) * 32;        // warp c-offset (4 warps over 128)
    int nw = (warp & 1) * 64;         // warp n-offset (2 warps over 128)
    int r  = lane & 15, q = lane >> 4;

    for (int t = 0; t < NT; ++t) {
        __half* Bp = (t & 1) ? B1 : B0;
        int n0 = (blockIdx.x * NT + t) * 128;

        // ---- wait own staged data, convert own region -> B[p]
        CP_WAIT0();
#pragma unroll
        for (int i = 0; i < 16; ++i) {
            int idx = i * 256 + tid;
            int k = idx >> 5, c4 = idx & 31;
            float4 v = *(const float4*)(Xs + k * 128 + c4 * 4);
            __half* ph = Bp + k * LDB + c4 * 4;
            *(__half2*)(ph)     = __floats2half2_rn(v.x, v.y);
            *(__half2*)(ph + 2) = __floats2half2_rn(v.z, v.w);
        }

        // ---- refill own Xs region for tile t+1 (nobody else reads it)
        if (t + 1 < NT) {
            int n0n = n0 + 128;
#pragma unroll
            for (int i = 0; i < 16; ++i) {
                int idx = i * 256 + tid;
                int k = idx >> 5, c4 = idx & 31;
                CP_ASYNC16(smem_u32(Xs + k * 128 + c4 * 4),
                           xb + (size_t)k * 65536 + n0n + c4 * 4);
            }
            CP_COMMIT();
        }

        __syncthreads();   // B[p] fully written (single barrier per tile)

        float acc[2][8][4];
#pragma unroll
        for (int mf = 0; mf < 2; ++mf)
#pragma unroll
            for (int nf = 0; nf < 8; ++nf)
#pragma unroll
                for (int e = 0; e < 4; ++e) acc[mf][nf][e] = 0.f;

#pragma unroll
        for (int ks = 0; ks < 8; ++ks) {
            int k0 = ks * 16;
            unsigned ah[2][4];
#pragma unroll
            for (int mf = 0; mf < 2; ++mf)
                LDSM_X4(ah[mf], smem_u32(Ahi + (mw + mf * 16 + r) * LDA + k0 + q * 8));
#pragma unroll
            for (int nc = 0; nc < 4; ++nc) {
                unsigned bf[4];
                LDSM_X4_T(bf, smem_u32(Bp + (k0 + r) * LDB + nw + nc * 16 + q * 8));
#pragma unroll
                for (int mf = 0; mf < 2; ++mf) {
#pragma unroll
                    for (int h = 0; h < 2; ++h) {
                        float* C = acc[mf][nc * 2 + h];
                        MMAF16(C, ah[mf], bf[2 * h], bf[2 * h + 1]);
                    }
                }
            }
        }

        // epilogue: store acc to gmem (no barrier; next convert uses other B buf)
        int rbase = mw + (lane >> 2);
        int cbase = nw + ((lane & 3) << 1);
#pragma unroll
        for (int mf = 0; mf < 2; ++mf) {
#pragma unroll
            for (int nf = 0; nf < 8; ++nf) {
                float* p0 = ob + (size_t)(rbase + mf * 16) * 65536 + n0 + cbase + nf * 8;
                float* p1 = p0 + 8ull * 65536;
                *(float2*)p0 = make_float2(acc[mf][nf][0], acc[mf][nf][1]);
                *(float2*)p1 = make_float2(acc[mf][nf][2], acc[mf][nf][3]);
            }
        }
    }
}

// ---------------- launch ----------------
extern "C" void kernel_launch(void* const* d_in, const int* in_sizes, int n_in,
                              void* d_out, int out_size)
{
    (void)in_sizes; (void)n_in; (void)out_size;
    const float* x    = (const float*)d_in[0];
    const float* c1w  = (const float*)d_in[1];
    const float* g1   = (const float*)d_in[2];
    const float* b1   = (const float*)d_in[3];
    const float* m1   = (const float*)d_in[4];
    const float* v1   = (const float*)d_in[5];
    const float* a1   = (const float*)d_in[6];
    const float* c2w  = (const float*)d_in[7];
    const float* g2   = (const float*)d_in[8];
    const float* b2   = (const float*)d_in[9];
    const float* m2   = (const float*)d_in[10];
    const float* v2   = (const float*)d_in[11];
    const float* a2   = (const float*)d_in[12];
    float* out = (float*)d_out;

    // fused pool smem: 67*256*4 + 33*128*4 = 68608 + 16896 = 85504
    cudaFuncSetAttribute(fused_pool_kernel,
                         cudaFuncAttributeMaxDynamicSharedMemorySize, 85504);
    cudaFuncSetAttribute(gram_partial_kernel,
                         cudaFuncAttributeMaxDynamicSharedMemorySize, 65536);
    // attn smem: A 128*136*2 + B 2*128*136*2 + stage 128*128*4 = 170112
    cudaFuncSetAttribute(attn_mma_kernel,
                         cudaFuncAttributeMaxDynamicSharedMemorySize, 170112);

    fused_pool_kernel<<<dim3(4, 1024), 256, 85504>>>(
        x, c1w, g1, b1, m1, v1, a1, c2w, g2, b2, m2, v2, a2);
    gram_partial_kernel<<<dim3(32, 8), 256, 65536>>>();
    softmax_kernel<<<dim3(128, 8), 128>>>();
    attn_mma_kernel<<<dim3(128, 8), 256, 170112>>>(x, out);
}

// round 8
// speedup vs baseline: 1.1367x; 1.1367x over previous
#include <cuda_runtime.h>
#include <cuda_fp16.h>
#include <cstdint>

#define EPSV 1e-5f

// ---------------- scratch (device globals; no allocation allowed) ----------------
__device__ float g_p1[8ull * 128 * 128 * 128];   // pooled stage 1: (B,C,128,128)
__device__ float g_p2[8ull * 128 * 64 * 64];     // pooled stage 2: (B,C,64,64)
__device__ float g_part[8ull * 32 * 128 * 128];  // gram partials: (B, 32 splits, C, C)
__device__ float g_St[8ull * 128 * 128];         // sim transposed: [b][c][k]

// ---------------- kernel 1/2: depthwise 3x3 s2 p1 + BN + PReLU ----------------
__global__ void dwconv_bn_prelu_kernel(
    const float* __restrict__ in, float* __restrict__ out,
    const float* __restrict__ w,
    const float* __restrict__ gamma, const float* __restrict__ beta,
    const float* __restrict__ mean, const float* __restrict__ var,
    const float* __restrict__ alpha,
    int Hin, int Win, int Hout, int Wout)
{
    int bc = blockIdx.z;           // b*128 + c
    int c  = bc & 127;
    int ox = blockIdx.x * 32 + threadIdx.x;
    int oy = blockIdx.y * 8 + threadIdx.y;

    const float* ip = in + (size_t)bc * Hin * Win;
    float w0 = w[c*9+0], w1 = w[c*9+1], w2 = w[c*9+2];
    float w3 = w[c*9+3], w4 = w[c*9+4], w5 = w[c*9+5];
    float w6 = w[c*9+6], w7 = w[c*9+7], w8 = w[c*9+8];
    float inv  = gamma[c] * rsqrtf(var[c] + EPSV);
    float bias = beta[c] - mean[c] * inv;
    float a    = alpha[c];

    int iy = 2 * oy - 1;
    int ix = 2 * ox - 1;
    bool top  = (iy >= 0);
    bool left = (ix >= 0);

    const float* r0 = ip + (size_t)iy * Win + ix;
    const float* r1 = r0 + Win;
    const float* r2 = r1 + Win;

    float s = 0.f;
    if (top) {
        if (left) s += w0 * r0[0];
        s += w1 * r0[1];
        s += w2 * r0[2];
    }
    if (left) s += w3 * r1[0];
    s += w4 * r1[1];
    s += w5 * r1[2];
    if (left) s += w6 * r2[0];
    s += w7 * r2[1];
    s += w8 * r2[2];

    float y = s * inv + bias;
    out[(size_t)bc * Hout * Wout + (size_t)oy * Wout + ox] = (y > 0.f) ? y : a * y;
}

// ---------------- kernel 3: gram partials ----------------
__global__ __launch_bounds__(256) void gram_partial_kernel()
{
    extern __shared__ float P[];       // [128 n][128 c]
    int s = blockIdx.x, b = blockIdx.y;
    int tid = threadIdx.x;

    const float* src = g_p2 + (size_t)b * 128 * 4096 + (size_t)s * 128;
    for (int idx = tid; idx < 4096; idx += 256) {
        int c = idx & 127, ng = idx >> 7;
        float4 v = *(const float4*)(src + (size_t)c * 4096 + ng * 4);
        P[(ng * 4 + 0) * 128 + c] = v.x;
        P[(ng * 4 + 1) * 128 + c] = v.y;
        P[(ng * 4 + 2) * 128 + c] = v.z;
        P[(ng * 4 + 3) * 128 + c] = v.w;
    }
    __syncthreads();

    int i0 = (tid >> 4) * 8;
    int j0 = (tid & 15) * 8;
    float acc[8][8];
#pragma unroll
    for (int ii = 0; ii < 8; ++ii)
#pragma unroll
        for (int jj = 0; jj < 8; ++jj) acc[ii][jj] = 0.f;

    for (int n = 0; n < 128; ++n) {
        const float* row = P + n * 128;
        float4 a0 = *(const float4*)(row + i0);
        float4 a1 = *(const float4*)(row + i0 + 4);
        float4 b0 = *(const float4*)(row + j0);
        float4 b1 = *(const float4*)(row + j0 + 4);
        float ai[8] = {a0.x, a0.y, a0.z, a0.w, a1.x, a1.y, a1.z, a1.w};
        float bj[8] = {b0.x, b0.y, b0.z, b0.w, b1.x, b1.y, b1.z, b1.w};
#pragma unroll
        for (int ii = 0; ii < 8; ++ii)
#pragma unroll
            for (int jj = 0; jj < 8; ++jj)
                acc[ii][jj] = fmaf(ai[ii], bj[jj], acc[ii][jj]);
    }

    float* dst = g_part + ((size_t)b * 32 + s) * 16384;
#pragma unroll
    for (int ii = 0; ii < 8; ++ii) {
        float4 v0 = make_float4(acc[ii][0], acc[ii][1], acc[ii][2], acc[ii][3]);
        float4 v1 = make_float4(acc[ii][4], acc[ii][5], acc[ii][6], acc[ii][7]);
        float* op = dst + (size_t)(i0 + ii) * 128 + j0;
        *(float4*)op = v0;
        *(float4*)(op + 4) = v1;
    }
}

// ---------------- kernel 4: reduce, scale, softmax; store TRANSPOSED sim ----
__global__ void softmax_kernel()
{
    int i = blockIdx.x, b = blockIdx.y, j = threadIdx.x;   // i = row k, j = col c
    const float* p = g_part + (size_t)b * 32 * 16384 + (size_t)i * 128 + j;
    float g = 0.f;
#pragma unroll
    for (int s = 0; s < 32; ++s) g += p[(size_t)s * 16384];
    g *= (1.0f / 64.0f);   // (64*64)^-0.5

    __shared__ float buf[128];
    buf[j] = g;
    __syncthreads();
    for (int off = 64; off > 0; off >>= 1) {
        if (j < off) buf[j] = fmaxf(buf[j], buf[j + off]);
        __syncthreads();
    }
    float m = buf[0];
    __syncthreads();
    float e = __expf(g - m);
    buf[j] = e;
    __syncthreads();
    for (int off = 64; off > 0; off >>= 1) {
        if (j < off) buf[j] = buf[j] + buf[j + off];
        __syncthreads();
    }
    float r = e / buf[0];
    g_St[(size_t)b * 16384 + (size_t)j * 128 + i] = r;   // [b][c][k]
}

// ---------------- kernel 5: out[b,c,n] = sum_k sim[b,k,c]*x[b,k,n], fp16 single-product MMA ----
#define LDA 136
#define LDB 136
#define NT  4   // n-tiles (128 wide) per block

__device__ __forceinline__ unsigned smem_u32(const void* p) {
    return (unsigned)__cvta_generic_to_shared(p);
}

#define LDSM_X4(r, addr) \
    asm volatile("ldmatrix.sync.aligned.m8n8.x4.shared.b16 {%0,%1,%2,%3},[%4];" \
        : "=r"((r)[0]), "=r"((r)[1]), "=r"((r)[2]), "=r"((r)[3]) : "r"(addr))

#define LDSM_X4_T(r, addr) \
    asm volatile("ldmatrix.sync.aligned.m8n8.x4.trans.shared.b16 {%0,%1,%2,%3},[%4];" \
        : "=r"((r)[0]), "=r"((r)[1]), "=r"((r)[2]), "=r"((r)[3]) : "r"(addr))

#define MMAF16(C, A, b0, b1) \
    asm volatile("mma.sync.aligned.m16n8k16.row.col.f32.f16.f16.f32 " \
        "{%0,%1,%2,%3},{%4,%5,%6,%7},{%8,%9},{%0,%1,%2,%3};" \
        : "+f"((C)[0]), "+f"((C)[1]), "+f"((C)[2]), "+f"((C)[3]) \
        : "r"((A)[0]), "r"((A)[1]), "r"((A)[2]), "r"((A)[3]), "r"(b0), "r"(b1))

#define CP_ASYNC16(dst, src) \
    asm volatile("cp.async.cg.shared.global [%0],[%1],16;" :: "r"(dst), "l"(src))
#define CP_COMMIT() asm volatile("cp.async.commit_group;")
#define CP_WAIT0()  asm volatile("cp.async.wait_group 0;" ::: "memory")

__global__ __launch_bounds__(256) void attn_mma_kernel(const float* __restrict__ x,
                                                       float* __restrict__ out)
{
    extern __shared__ char smraw[];
    __half* Ahi = (__half*)smraw;              // [128 c][LDA k]
    __half* B0  = Ahi + 128 * LDA;             // [128 k][LDB n], double buffered
    __half* B1  = B0 + 128 * LDB;
    float*  Xs  = (float*)(B1 + 128 * LDB);    // staging [128 k][128 n] fp32

    int b    = blockIdx.y;
    int tid  = threadIdx.x;
    int warp = tid >> 5, lane = tid & 31;

    const float* xb = x + (size_t)b * 128 * 65536;
    float*       ob = out + (size_t)b * 128 * 65536;

    // ---- prefetch tile 0 via cp.async (each thread owns a fixed Xs region)
    {
        int n0 = blockIdx.x * NT * 128;
#pragma unroll
        for (int i = 0; i < 16; ++i) {
            int idx = i * 256 + tid;
            int k = idx >> 5, c4 = idx & 31;
            CP_ASYNC16(smem_u32(Xs + k * 128 + c4 * 4),
                       xb + (size_t)k * 65536 + n0 + c4 * 4);
        }
        CP_COMMIT();
    }

    // ---- A prep: g_St[b] ([c][k] fp32) -> fp16
    {
        const float* Sp = g_St + (size_t)b * 16384;
#pragma unroll
        for (int i = 0; i < 16; ++i) {
            int idx = i * 256 + tid;
            int c = idx >> 5, k4 = (idx & 31) * 4;
            float4 v = *(const float4*)(Sp + c * 128 + k4);
            __half* ph = Ahi + c * LDA + k4;
            *(__half2*)(ph)     = __floats2half2_rn(v.x, v.y);
            *(__half2*)(ph + 2) = __floats2half2_rn(v.z, v.w);
        }
    }

    int mw = (warp >> 1) * 32;        // warp c-offset (4 warps over 128)
    int nw = (warp & 1) * 64;         // warp n-offset (2 warps over 128)
    int r  = lane & 15, q = lane >> 4;

    for (int t = 0; t < NT; ++t) {
        __half* Bp = (t & 1) ? B1 : B0;
        int n0 = (blockIdx.x * NT + t) * 128;

        // ---- wait own staged data, convert own region -> B[p]
        CP_WAIT0();
#pragma unroll
        for (int i = 0; i < 16; ++i) {
            int idx = i * 256 + tid;
            int k = idx >> 5, c4 = idx & 31;
            float4 v = *(const float4*)(Xs + k * 128 + c4 * 4);
            __half* ph = Bp + k * LDB + c4 * 4;
            *(__half2*)(ph)     = __floats2half2_rn(v.x, v.y);
            *(__half2*)(ph + 2) = __floats2half2_rn(v.z, v.w);
        }

        // ---- refill own Xs region for tile t+1 (nobody else reads it)
        if (t + 1 < NT) {
            int n0n = n0 + 128;
#pragma unroll
            for (int i = 0; i < 16; ++i) {
                int idx = i * 256 + tid;
                int k = idx >> 5, c4 = idx & 31;
                CP_ASYNC16(smem_u32(Xs + k * 128 + c4 * 4),
                           xb + (size_t)k * 65536 + n0n + c4 * 4);
            }
            CP_COMMIT();
        }

        __syncthreads();   // B[p] fully written (single barrier per tile)

        float acc[2][8][4];
#pragma unroll
        for (int mf = 0; mf < 2; ++mf)
#pragma unroll
            for (int nf = 0; nf < 8; ++nf)
#pragma unroll
                for (int e = 0; e < 4; ++e) acc[mf][nf][e] = 0.f;

#pragma unroll
        for (int ks = 0; ks < 8; ++ks) {
            int k0 = ks * 16;
            unsigned ah[2][4];
#pragma unroll
            for (int mf = 0; mf < 2; ++mf)
                LDSM_X4(ah[mf], smem_u32(Ahi + (mw + mf * 16 + r) * LDA + k0 + q * 8));
#pragma unroll
            for (int nc = 0; nc < 4; ++nc) {
                unsigned bf[4];
                LDSM_X4_T(bf, smem_u32(Bp + (k0 + r) * LDB + nw + nc * 16 + q * 8));
#pragma unroll
                for (int mf = 0; mf < 2; ++mf) {
#pragma unroll
                    for (int h = 0; h < 2; ++h) {
                        float* C = acc[mf][nc * 2 + h];
                        MMAF16(C, ah[mf], bf[2 * h], bf[2 * h + 1]);
                    }
                }
            }
        }

        // epilogue: store acc to gmem (no barrier; next convert uses other B buf)
        int rbase = mw + (lane >> 2);
        int cbase = nw + ((lane & 3) << 1);
#pragma unroll
        for (int mf = 0; mf < 2; ++mf) {
#pragma unroll
            for (int nf = 0; nf < 8; ++nf) {
                float* p0 = ob + (size_t)(rbase + mf * 16) * 65536 + n0 + cbase + nf * 8;
                float* p1 = p0 + 8ull * 65536;
                *(float2*)p0 = make_float2(acc[mf][nf][0], acc[mf][nf][1]);
                *(float2*)p1 = make_float2(acc[mf][nf][2], acc[mf][nf][3]);
            }
        }
    }
}

// ---------------- launch ----------------
extern "C" void kernel_launch(void* const* d_in, const int* in_sizes, int n_in,
                              void* d_out, int out_size)
{
    (void)in_sizes; (void)n_in; (void)out_size;
    const float* x    = (const float*)d_in[0];
    const float* c1w  = (const float*)d_in[1];
    const float* g1   = (const float*)d_in[2];
    const float* b1   = (const float*)d_in[3];
    const float* m1   = (const float*)d_in[4];
    const float* v1   = (const float*)d_in[5];
    const float* a1   = (const float*)d_in[6];
    const float* c2w  = (const float*)d_in[7];
    const float* g2   = (const float*)d_in[8];
    const float* b2   = (const float*)d_in[9];
    const float* m2   = (const float*)d_in[10];
    const float* v2   = (const float*)d_in[11];
    const float* a2   = (const float*)d_in[12];
    float* out = (float*)d_out;

    void* tmp;
    cudaGetSymbolAddress(&tmp, g_p1);  float* p1 = (float*)tmp;
    cudaGetSymbolAddress(&tmp, g_p2);  float* p2 = (float*)tmp;

    cudaFuncSetAttribute(gram_partial_kernel,
                         cudaFuncAttributeMaxDynamicSharedMemorySize, 65536);
    // attn smem: A 128*136*2 + B double 2*128*136*2 + stage 128*128*4 = 170112
    cudaFuncSetAttribute(attn_mma_kernel,
                         cudaFuncAttributeMaxDynamicSharedMemorySize, 170112);

    dim3 blk(32, 8);
    dwconv_bn_prelu_kernel<<<dim3(4, 16, 1024), blk>>>(x, p1, c1w, g1, b1, m1, v1, a1,
                                                       256, 256, 128, 128);
    dwconv_bn_prelu_kernel<<<dim3(2, 8, 1024), blk>>>(p1, p2, c2w, g2, b2, m2, v2, a2,
                                                      128, 128, 64, 64);
    gram_partial_kernel<<<dim3(32, 8), 256, 65536>>>();
    softmax_kernel<<<dim3(128, 8), 128>>>();
    attn_mma_kernel<<<dim3(128, 8), 256, 170112>>>(x, out);
}

// round 9
// speedup vs baseline: 1.4723x; 1.2952x over previous
#include <cuda_runtime.h>
#include <cuda_fp16.h>
#include <cstdint>

#define EPSV 1e-5f

// ---------------- scratch (device globals; no allocation allowed) ----------------
__device__ float g_p1[8ull * 128 * 128 * 128];   // pooled stage 1: (B,C,128,128)
__device__ float g_p2[8ull * 128 * 64 * 64];     // pooled stage 2: (B,C,64,64)
__device__ float g_part[8ull * 32 * 128 * 128];  // gram partials: (B, 32 splits, C, C)
__device__ float g_St[8ull * 128 * 128];         // sim transposed: [b][c][k]

// ---------------- kernel 1/2: depthwise 3x3 s2 p1 + BN + PReLU, 4-wide ----------------
// Each thread: 4 consecutive outputs from 9 aligned LDG.128 (3 float4 per input row).
__device__ __forceinline__ void load_row9(float* f, const float* rowp, int tx)
{
    float4 A = (tx > 0) ? *(const float4*)(rowp + tx * 8 - 4)
                        : make_float4(0.f, 0.f, 0.f, 0.f);
    float4 B = *(const float4*)(rowp + tx * 8);
    float4 C = *(const float4*)(rowp + tx * 8 + 4);
    f[0] = A.w;
    f[1] = B.x; f[2] = B.y; f[3] = B.z; f[4] = B.w;
    f[5] = C.x; f[6] = C.y; f[7] = C.z; f[8] = C.w;
}

__global__ void dwconv_v4_kernel(
    const float* __restrict__ in, float* __restrict__ out,
    const float* __restrict__ w,
    const float* __restrict__ gamma, const float* __restrict__ beta,
    const float* __restrict__ mean, const float* __restrict__ var,
    const float* __restrict__ alpha,
    int Win, int Wout, int Hout)
{
    int bc = blockIdx.z;           // b*128 + c
    int c  = bc & 127;
    int tx = threadIdx.x;          // Wout/4 threads wide
    int oy = blockIdx.x * blockDim.y + threadIdx.y;

    const float* ip = in + (size_t)bc * (size_t)(4 * Hout * Wout);  // Hin*Win

    float w0 = w[c*9+0], w1 = w[c*9+1], w2 = w[c*9+2];
    float w3 = w[c*9+3], w4 = w[c*9+4], w5 = w[c*9+5];
    float w6 = w[c*9+6], w7 = w[c*9+7], w8 = w[c*9+8];
    float inv  = gamma[c] * rsqrtf(var[c] + EPSV);
    float bias = beta[c] - mean[c] * inv;
    float a    = alpha[c];

    int iy = 2 * oy;
    float f0[9], f1[9], f2[9];
    if (oy > 0) load_row9(f0, ip + (size_t)(iy - 1) * Win, tx);
    else {
#pragma unroll
        for (int i = 0; i < 9; ++i) f0[i] = 0.f;
    }
    load_row9(f1, ip + (size_t)iy * Win, tx);
    load_row9(f2, ip + (size_t)(iy + 1) * Win, tx);

    float4 o;
    float* res = &o.x;
#pragma unroll
    for (int j = 0; j < 4; ++j) {
        float s = w0 * f0[2*j] + w1 * f0[2*j+1] + w2 * f0[2*j+2]
                + w3 * f1[2*j] + w4 * f1[2*j+1] + w5 * f1[2*j+2]
                + w6 * f2[2*j] + w7 * f2[2*j+1] + w8 * f2[2*j+2];
        float y = s * inv + bias;
        res[j] = (y > 0.f) ? y : a * y;
    }
    *(float4*)(out + (size_t)bc * Hout * Wout + (size_t)oy * Wout + tx * 4) = o;
}

// ---------------- kernel 3: gram partials ----------------
__global__ __launch_bounds__(256) void gram_partial_kernel()
{
    extern __shared__ float P[];       // [128 n][128 c]
    int s = blockIdx.x, b = blockIdx.y;
    int tid = threadIdx.x;

    const float* src = g_p2 + (size_t)b * 128 * 4096 + (size_t)s * 128;
    for (int idx = tid; idx < 4096; idx += 256) {
        int c = idx & 127, ng = idx >> 7;
        float4 v = *(const float4*)(src + (size_t)c * 4096 + ng * 4);
        P[(ng * 4 + 0) * 128 + c] = v.x;
        P[(ng * 4 + 1) * 128 + c] = v.y;
        P[(ng * 4 + 2) * 128 + c] = v.z;
        P[(ng * 4 + 3) * 128 + c] = v.w;
    }
    __syncthreads();

    int i0 = (tid >> 4) * 8;
    int j0 = (tid & 15) * 8;
    float acc[8][8];
#pragma unroll
    for (int ii = 0; ii < 8; ++ii)
#pragma unroll
        for (int jj = 0; jj < 8; ++jj) acc[ii][jj] = 0.f;

    for (int n = 0; n < 128; ++n) {
        const float* row = P + n * 128;
        float4 a0 = *(const float4*)(row + i0);
        float4 a1 = *(const float4*)(row + i0 + 4);
        float4 b0 = *(const float4*)(row + j0);
        float4 b1 = *(const float4*)(row + j0 + 4);
        float ai[8] = {a0.x, a0.y, a0.z, a0.w, a1.x, a1.y, a1.z, a1.w};
        float bj[8] = {b0.x, b0.y, b0.z, b0.w, b1.x, b1.y, b1.z, b1.w};
#pragma unroll
        for (int ii = 0; ii < 8; ++ii)
#pragma unroll
            for (int jj = 0; jj < 8; ++jj)
                acc[ii][jj] = fmaf(ai[ii], bj[jj], acc[ii][jj]);
    }

    float* dst = g_part + ((size_t)b * 32 + s) * 16384;
#pragma unroll
    for (int ii = 0; ii < 8; ++ii) {
        float4 v0 = make_float4(acc[ii][0], acc[ii][1], acc[ii][2], acc[ii][3]);
        float4 v1 = make_float4(acc[ii][4], acc[ii][5], acc[ii][6], acc[ii][7]);
        float* op = dst + (size_t)(i0 + ii) * 128 + j0;
        *(float4*)op = v0;
        *(float4*)(op + 4) = v1;
    }
}

// ---------------- kernel 4: reduce, scale, softmax; store TRANSPOSED sim ----
__global__ void softmax_kernel()
{
    int i = blockIdx.x, b = blockIdx.y, j = threadIdx.x;   // i = row k, j = col c
    const float* p = g_part + (size_t)b * 32 * 16384 + (size_t)i * 128 + j;
    float g = 0.f;
#pragma unroll
    for (int s = 0; s < 32; ++s) g += p[(size_t)s * 16384];
    g *= (1.0f / 64.0f);   // (64*64)^-0.5

    __shared__ float buf[128];
    buf[j] = g;
    __syncthreads();
    for (int off = 64; off > 0; off >>= 1) {
        if (j < off) buf[j] = fmaxf(buf[j], buf[j + off]);
        __syncthreads();
    }
    float m = buf[0];
    __syncthreads();
    float e = __expf(g - m);
    buf[j] = e;
    __syncthreads();
    for (int off = 64; off > 0; off >>= 1) {
        if (j < off) buf[j] = buf[j] + buf[j + off];
        __syncthreads();
    }
    float r = e / buf[0];
    g_St[(size_t)b * 16384 + (size_t)j * 128 + i] = r;   // [b][c][k]
}

// ---------------- kernel 5: out[b,c,n] = sum_k sim[b,k,c]*x[b,k,n], fp16 MMA, 64-n tiles ----
#define LDA 136
#define LDB 72
#define TN  64
#define NSUB 8   // n-subtiles (64 wide) per block -> 512 n per block

__device__ __forceinline__ unsigned smem_u32(const void* p) {
    return (unsigned)__cvta_generic_to_shared(p);
}

#define LDSM_X4(r, addr) \
    asm volatile("ldmatrix.sync.aligned.m8n8.x4.shared.b16 {%0,%1,%2,%3},[%4];" \
        : "=r"((r)[0]), "=r"((r)[1]), "=r"((r)[2]), "=r"((r)[3]) : "r"(addr))

#define LDSM_X4_T(r, addr) \
    asm volatile("ldmatrix.sync.aligned.m8n8.x4.trans.shared.b16 {%0,%1,%2,%3},[%4];" \
        : "=r"((r)[0]), "=r"((r)[1]), "=r"((r)[2]), "=r"((r)[3]) : "r"(addr))

#define MMAF16(C, A, b0, b1) \
    asm volatile("mma.sync.aligned.m16n8k16.row.col.f32.f16.f16.f32 " \
        "{%0,%1,%2,%3},{%4,%5,%6,%7},{%8,%9},{%0,%1,%2,%3};" \
        : "+f"((C)[0]), "+f"((C)[1]), "+f"((C)[2]), "+f"((C)[3]) \
        : "r"((A)[0]), "r"((A)[1]), "r"((A)[2]), "r"((A)[3]), "r"(b0), "r"(b1))

#define CP_ASYNC16(dst, src) \
    asm volatile("cp.async.cg.shared.global [%0],[%1],16;" :: "r"(dst), "l"(src))
#define CP_COMMIT() asm volatile("cp.async.commit_group;")
#define CP_WAIT0()  asm volatile("cp.async.wait_group 0;" ::: "memory")

// smem: A 128*136*2 + B double 2*128*72*2 + Xs 128*64*4 = 34816+36864+32768 = 104448
#define ATTN_SMEM 104448

__global__ __launch_bounds__(256, 2) void attn_mma_kernel(const float* __restrict__ x,
                                                          float* __restrict__ out)
{
    extern __shared__ char smraw[];
    __half* Ahi = (__half*)smraw;              // [128 c][LDA k]
    __half* B0  = Ahi + 128 * LDA;             // [128 k][LDB n], double buffered
    __half* B1  = B0 + 128 * LDB;
    float*  Xs  = (float*)(B1 + 128 * LDB);    // staging [128 k][64 n] fp32

    int b    = blockIdx.y;
    int tid  = threadIdx.x;
    int warp = tid >> 5, lane = tid & 31;

    const float* xb = x + (size_t)b * 128 * 65536;
    float*       ob = out + (size_t)b * 128 * 65536;

    // ---- prefetch subtile 0 (each thread owns a fixed Xs region: 8 chunks of 16B)
    {
        int n0 = blockIdx.x * (NSUB * TN);
#pragma unroll
        for (int i = 0; i < 8; ++i) {
            int idx = i * 256 + tid;
            int k = idx >> 4, c4 = idx & 15;
            CP_ASYNC16(smem_u32(Xs + k * TN + c4 * 4),
                       xb + (size_t)k * 65536 + n0 + c4 * 4);
        }
        CP_COMMIT();
    }

    // ---- A prep: g_St[b] ([c][k] fp32) -> fp16
    {
        const float* Sp = g_St + (size_t)b * 16384;
#pragma unroll
        for (int i = 0; i < 16; ++i) {
            int idx = i * 256 + tid;
            int c = idx >> 5, k4 = (idx & 31) * 4;
            float4 v = *(const float4*)(Sp + c * 128 + k4);
            __half* ph = Ahi + c * LDA + k4;
            *(__half2*)(ph)     = __floats2half2_rn(v.x, v.y);
            *(__half2*)(ph + 2) = __floats2half2_rn(v.z, v.w);
        }
    }

    int mw = (warp >> 1) * 32;        // warp c-offset (4 warps over 128)
    int nw = (warp & 1) * 32;         // warp n-offset (2 warps over 64)
    int r  = lane & 15, q = lane >> 4;

    for (int t = 0; t < NSUB; ++t) {
        __half* Bp = (t & 1) ? B1 : B0;
        int n0 = (blockIdx.x * NSUB + t) * TN;

        // ---- wait own staged data, convert own region -> B[p]
        CP_WAIT0();
#pragma unroll
        for (int i = 0; i < 8; ++i) {
            int idx = i * 256 + tid;
            int k = idx >> 4, c4 = idx & 15;
            float4 v = *(const float4*)(Xs + k * TN + c4 * 4);
            __half* ph = Bp + k * LDB + c4 * 4;
            *(__half2*)(ph)     = __floats2half2_rn(v.x, v.y);
            *(__half2*)(ph + 2) = __floats2half2_rn(v.z, v.w);
        }

        // ---- refill own Xs region for subtile t+1 (nobody else reads it)
        if (t + 1 < NSUB) {
            int n0n = n0 + TN;
#pragma unroll
            for (int i = 0; i < 8; ++i) {
                int idx = i * 256 + tid;
                int k = idx >> 4, c4 = idx & 15;
                CP_ASYNC16(smem_u32(Xs + k * TN + c4 * 4),
                           xb + (size_t)k * 65536 + n0n + c4 * 4);
            }
            CP_COMMIT();
        }

        __syncthreads();   // B[p] fully written (single barrier per subtile)

        float acc[2][4][4];
#pragma unroll
        for (int mf = 0; mf < 2; ++mf)
#pragma unroll
            for (int nf = 0; nf < 4; ++nf)
#pragma unroll
                for (int e = 0; e < 4; ++e) acc[mf][nf][e] = 0.f;

#pragma unroll
        for (int ks = 0; ks < 8; ++ks) {
            int k0 = ks * 16;
            unsigned ah[2][4];
#pragma unroll
            for (int mf = 0; mf < 2; ++mf)
                LDSM_X4(ah[mf], smem_u32(Ahi + (mw + mf * 16 + r) * LDA + k0 + q * 8));
#pragma unroll
            for (int nc = 0; nc < 2; ++nc) {
                unsigned bf[4];
                LDSM_X4_T(bf, smem_u32(Bp + (k0 + r) * LDB + nw + nc * 16 + q * 8));
#pragma unroll
                for (int mf = 0; mf < 2; ++mf) {
#pragma unroll
                    for (int h = 0; h < 2; ++h) {
                        float* C = acc[mf][nc * 2 + h];
                        MMAF16(C, ah[mf], bf[2 * h], bf[2 * h + 1]);
                    }
                }
            }
        }

        // epilogue: store acc to gmem (no barrier; next convert uses other B buf)
        int rbase = mw + (lane >> 2);
        int cbase = nw + ((lane & 3) << 1);
#pragma unroll
        for (int mf = 0; mf < 2; ++mf) {
#pragma unroll
            for (int nf = 0; nf < 4; ++nf) {
                float* p0 = ob + (size_t)(rbase + mf * 16) * 65536 + n0 + cbase + nf * 8;
                float* p1 = p0 + 8ull * 65536;
                *(float2*)p0 = make_float2(acc[mf][nf][0], acc[mf][nf][1]);
                *(float2*)p1 = make_float2(acc[mf][nf][2], acc[mf][nf][3]);
            }
        }
    }
}

// ---------------- launch ----------------
extern "C" void kernel_launch(void* const* d_in, const int* in_sizes, int n_in,
                              void* d_out, int out_size)
{
    (void)in_sizes; (void)n_in; (void)out_size;
    const float* x    = (const float*)d_in[0];
    const float* c1w  = (const float*)d_in[1];
    const float* g1   = (const float*)d_in[2];
    const float* b1   = (const float*)d_in[3];
    const float* m1   = (const float*)d_in[4];
    const float* v1   = (const float*)d_in[5];
    const float* a1   = (const float*)d_in[6];
    const float* c2w  = (const float*)d_in[7];
    const float* g2   = (const float*)d_in[8];
    const float* b2   = (const float*)d_in[9];
    const float* m2   = (const float*)d_in[10];
    const float* v2   = (const float*)d_in[11];
    const float* a2   = (const float*)d_in[12];
    float* out = (float*)d_out;

    void* tmp;
    cudaGetSymbolAddress(&tmp, g_p1);  float* p1 = (float*)tmp;
    cudaGetSymbolAddress(&tmp, g_p2);  float* p2 = (float*)tmp;

    cudaFuncSetAttribute(gram_partial_kernel,
                         cudaFuncAttributeMaxDynamicSharedMemorySize, 65536);
    cudaFuncSetAttribute(attn_mma_kernel,
                         cudaFuncAttributeMaxDynamicSharedMemorySize, ATTN_SMEM);

    // conv1: 256x256 -> 128x128; 32 threads wide (x4), 8 rows/block
    dwconv_v4_kernel<<<dim3(16, 1, 1024), dim3(32, 8)>>>(
        x, p1, c1w, g1, b1, m1, v1, a1, 256, 128, 128);
    // conv2: 128x128 -> 64x64; 16 threads wide (x4), 16 rows/block
    dwconv_v4_kernel<<<dim3(4, 1, 1024), dim3(16, 16)>>>(
        p1, p2, c2w, g2, b2, m2, v2, a2, 128, 64, 64);
    gram_partial_kernel<<<dim3(32, 8), 256, 65536>>>();
    softmax_kernel<<<dim3(128, 8), 128>>>();
    attn_mma_kernel<<<dim3(128, 8), 256, ATTN_SMEM>>>(x, out);
}

// round 10
// speedup vs baseline: 1.7653x; 1.1990x over previous
#include <cuda_runtime.h>
#include <cuda_fp16.h>
#include <cstdint>

#define EPSV 1e-5f

// ---------------- scratch (device globals; no allocation allowed) ----------------
__device__ __half g_p1h[8ull * 128 * 128 * 128];  // pooled stage 1 fp16: (B,C,128,128)
__device__ __half g_p2h[8ull * 128 * 64 * 64];    // pooled stage 2 fp16: (B,C,4096)
__device__ float  g_part[8ull * 16 * 128 * 128];  // gram partials: (B, 16 splits, C, C)
__device__ float  g_St[8ull * 128 * 128];         // sim transposed: [b][c][k]

// ---------------- kernel 1: dwconv s2 + BN + PReLU, fp32 in -> fp16 out ----------------
__device__ __forceinline__ void load_row9(float* f, const float* rowp, int tx)
{
    float4 A = (tx > 0) ? *(const float4*)(rowp + tx * 8 - 4)
                        : make_float4(0.f, 0.f, 0.f, 0.f);
    float4 B = *(const float4*)(rowp + tx * 8);
    float4 C = *(const float4*)(rowp + tx * 8 + 4);
    f[0] = A.w;
    f[1] = B.x; f[2] = B.y; f[3] = B.z; f[4] = B.w;
    f[5] = C.x; f[6] = C.y; f[7] = C.z; f[8] = C.w;
}

__global__ void dwconv1_kernel(
    const float* __restrict__ in, __half* __restrict__ out,
    const float* __restrict__ w,
    const float* __restrict__ gamma, const float* __restrict__ beta,
    const float* __restrict__ mean, const float* __restrict__ var,
    const float* __restrict__ alpha)
{
    const int Win = 256, Wout = 128, Hout = 128;
    int bc = blockIdx.z;
    int c  = bc & 127;
    int tx = threadIdx.x;                       // 32 threads x 4 outputs
    int oy = blockIdx.x * blockDim.y + threadIdx.y;

    const float* ip = in + (size_t)bc * 65536;

    float w0 = w[c*9+0], w1 = w[c*9+1], w2 = w[c*9+2];
    float w3 = w[c*9+3], w4 = w[c*9+4], w5 = w[c*9+5];
    float w6 = w[c*9+6], w7 = w[c*9+7], w8 = w[c*9+8];
    float inv  = gamma[c] * rsqrtf(var[c] + EPSV);
    float bias = beta[c] - mean[c] * inv;
    float a    = alpha[c];

    int iy = 2 * oy;
    float f0[9], f1[9], f2[9];
    if (oy > 0) load_row9(f0, ip + (size_t)(iy - 1) * Win, tx);
    else {
#pragma unroll
        for (int i = 0; i < 9; ++i) f0[i] = 0.f;
    }
    load_row9(f1, ip + (size_t)iy * Win, tx);
    load_row9(f2, ip + (size_t)(iy + 1) * Win, tx);

    float res[4];
#pragma unroll
    for (int j = 0; j < 4; ++j) {
        float s = w0 * f0[2*j] + w1 * f0[2*j+1] + w2 * f0[2*j+2]
                + w3 * f1[2*j] + w4 * f1[2*j+1] + w5 * f1[2*j+2]
                + w6 * f2[2*j] + w7 * f2[2*j+1] + w8 * f2[2*j+2];
        float y = s * inv + bias;
        res[j] = (y > 0.f) ? y : a * y;
    }
    __half2 h0 = __floats2half2_rn(res[0], res[1]);
    __half2 h1 = __floats2half2_rn(res[2], res[3]);
    __half* op = out + (size_t)bc * (Hout * Wout) + (size_t)oy * Wout + tx * 4;
    *(__half2*)op       = h0;
    *(__half2*)(op + 2) = h1;
}

// ---------------- kernel 2: dwconv s2 + BN + PReLU, fp16 in -> fp16 out ----------------
__device__ __forceinline__ void load_row9h(float* f, const __half* rowp, int tx)
{
    // elements 8tx-1 .. 8tx+7
    if (tx > 0) {
        __half2 pv = *(const __half2*)(rowp + tx * 8 - 2);
        f[0] = __half2float(__high2half(pv));
    } else f[0] = 0.f;
    uint4 B = *(const uint4*)(rowp + tx * 8);
    const __half2* hb = (const __half2*)&B;
#pragma unroll
    for (int i = 0; i < 4; ++i) {
        float2 v = __half22float2(hb[i]);
        f[1 + 2*i] = v.x;
        f[2 + 2*i] = v.y;
    }
}

__global__ void dwconv2_kernel(
    const __half* __restrict__ in, __half* __restrict__ out,
    const float* __restrict__ w,
    const float* __restrict__ gamma, const float* __restrict__ beta,
    const float* __restrict__ mean, const float* __restrict__ var,
    const float* __restrict__ alpha)
{
    const int Win = 128, Wout = 64, Hout = 64;
    int bc = blockIdx.z;
    int c  = bc & 127;
    int tx = threadIdx.x;                       // 16 threads x 4 outputs
    int oy = blockIdx.x * blockDim.y + threadIdx.y;

    const __half* ip = in + (size_t)bc * 16384;

    float w0 = w[c*9+0], w1 = w[c*9+1], w2 = w[c*9+2];
    float w3 = w[c*9+3], w4 = w[c*9+4], w5 = w[c*9+5];
    float w6 = w[c*9+6], w7 = w[c*9+7], w8 = w[c*9+8];
    float inv  = gamma[c] * rsqrtf(var[c] + EPSV);
    float bias = beta[c] - mean[c] * inv;
    float a    = alpha[c];

    int iy = 2 * oy;
    float f0[9], f1[9], f2[9];
    if (oy > 0) load_row9h(f0, ip + (size_t)(iy - 1) * Win, tx);
    else {
#pragma unroll
        for (int i = 0; i < 9; ++i) f0[i] = 0.f;
    }
    load_row9h(f1, ip + (size_t)iy * Win, tx);
    load_row9h(f2, ip + (size_t)(iy + 1) * Win, tx);

    float res[4];
#pragma unroll
    for (int j = 0; j < 4; ++j) {
        float s = w0 * f0[2*j] + w1 * f0[2*j+1] + w2 * f0[2*j+2]
                + w3 * f1[2*j] + w4 * f1[2*j+1] + w5 * f1[2*j+2]
                + w6 * f2[2*j] + w7 * f2[2*j+1] + w8 * f2[2*j+2];
        float y = s * inv + bias;
        res[j] = (y > 0.f) ? y : a * y;
    }
    __half2 h0 = __floats2half2_rn(res[0], res[1]);
    __half2 h1 = __floats2half2_rn(res[2], res[3]);
    __half* op = out + (size_t)bc * (Hout * Wout) + (size_t)oy * Wout + tx * 4;
    *(__half2*)op       = h0;
    *(__half2*)(op + 2) = h1;
}

// ---------------- common MMA helpers ----------------
__device__ __forceinline__ unsigned smem_u32(const void* p) {
    return (unsigned)__cvta_generic_to_shared(p);
}

#define LDSM_X4(r, addr) \
    asm volatile("ldmatrix.sync.aligned.m8n8.x4.shared.b16 {%0,%1,%2,%3},[%4];" \
        : "=r"((r)[0]), "=r"((r)[1]), "=r"((r)[2]), "=r"((r)[3]) : "r"(addr))

#define LDSM_X4_T(r, addr) \
    asm volatile("ldmatrix.sync.aligned.m8n8.x4.trans.shared.b16 {%0,%1,%2,%3},[%4];" \
        : "=r"((r)[0]), "=r"((r)[1]), "=r"((r)[2]), "=r"((r)[3]) : "r"(addr))

#define MMAF16(C, A, b0, b1) \
    asm volatile("mma.sync.aligned.m16n8k16.row.col.f32.f16.f16.f32 " \
        "{%0,%1,%2,%3},{%4,%5,%6,%7},{%8,%9},{%0,%1,%2,%3};" \
        : "+f"((C)[0]), "+f"((C)[1]), "+f"((C)[2]), "+f"((C)[3]) \
        : "r"((A)[0]), "r"((A)[1]), "r"((A)[2]), "r"((A)[3]), "r"(b0), "r"(b1))

#define CP_ASYNC16(dst, src) \
    asm volatile("cp.async.cg.shared.global [%0],[%1],16;" :: "r"(dst), "l"(src))
#define CP_COMMIT() asm volatile("cp.async.commit_group;")
#define CP_WAIT0()  asm volatile("cp.async.wait_group 0;" ::: "memory")

// ---------------- kernel 3: gram partials via fp16 MMA ----------------
// Block (s, b): G_s[i][j] = sum_{n in [s*256, s*256+256)} p2[i][n] p2[j][n]
#define LDP 264

__global__ __launch_bounds__(256) void gram_mma_kernel()
{
    extern __shared__ __half P[];       // [128 c][LDP]
    int s = blockIdx.x, b = blockIdx.y;
    int tid = threadIdx.x, warp = tid >> 5, lane = tid & 31;

    const __half* src = g_p2h + (size_t)b * 128 * 4096 + s * 256;
#pragma unroll
    for (int i = 0; i < 16; ++i) {
        int idx = i * 256 + tid;
        int c = idx >> 5, j = idx & 31;
        *(uint4*)(P + c * LDP + j * 8) = *(const uint4*)(src + (size_t)c * 4096 + j * 8);
    }
    __syncthreads();

    int i0 = (warp >> 1) * 32;
    int j0 = (warp & 1) * 64;
    int r  = lane & 15, q = lane >> 4;
    int br = (lane & 7) | ((lane >> 4) << 3);
    int bq = (lane >> 3) & 1;

    float acc[2][8][4];
#pragma unroll
    for (int mf = 0; mf < 2; ++mf)
#pragma unroll
        for (int nf = 0; nf < 8; ++nf)
#pragma unroll
            for (int e = 0; e < 4; ++e) acc[mf][nf][e] = 0.f;

#pragma unroll
    for (int ks = 0; ks < 16; ++ks) {
        int k0 = ks * 16;
        unsigned ah[2][4];
#pragma unroll
        for (int mf = 0; mf < 2; ++mf)
            LDSM_X4(ah[mf], smem_u32(P + (i0 + mf * 16 + r) * LDP + k0 + q * 8));
#pragma unroll
        for (int nc = 0; nc < 4; ++nc) {
            unsigned bf[4];
            LDSM_X4(bf, smem_u32(P + (j0 + nc * 16 + br) * LDP + k0 + bq * 8));
#pragma unroll
            for (int mf = 0; mf < 2; ++mf) {
                MMAF16(acc[mf][nc * 2],     ah[mf], bf[0], bf[1]);
                MMAF16(acc[mf][nc * 2 + 1], ah[mf], bf[2], bf[3]);
            }
        }
    }

    float* dst = g_part + ((size_t)b * 16 + s) * 16384;
    int rbase = i0 + (lane >> 2);
    int cbase = j0 + ((lane & 3) << 1);
#pragma unroll
    for (int mf = 0; mf < 2; ++mf) {
#pragma unroll
        for (int nf = 0; nf < 8; ++nf) {
            float* p0 = dst + (size_t)(rbase + mf * 16) * 128 + cbase + nf * 8;
            float* p1 = p0 + 8 * 128;
            *(float2*)p0 = make_float2(acc[mf][nf][0], acc[mf][nf][1]);
            *(float2*)p1 = make_float2(acc[mf][nf][2], acc[mf][nf][3]);
        }
    }
}

// ---------------- kernel 4: reduce 16 partials, scale, softmax; store TRANSPOSED ----
__global__ void softmax_kernel()
{
    int i = blockIdx.x, b = blockIdx.y, j = threadIdx.x;   // i = row k, j = col c
    const float* p = g_part + (size_t)b * 16 * 16384 + (size_t)i * 128 + j;
    float g = 0.f;
#pragma unroll
    for (int s = 0; s < 16; ++s) g += p[(size_t)s * 16384];
    g *= (1.0f / 64.0f);   // (64*64)^-0.5

    __shared__ float buf[128];
    buf[j] = g;
    __syncthreads();
    for (int off = 64; off > 0; off >>= 1) {
        if (j < off) buf[j] = fmaxf(buf[j], buf[j + off]);
        __syncthreads();
    }
    float m = buf[0];
    __syncthreads();
    float e = __expf(g - m);
    buf[j] = e;
    __syncthreads();
    for (int off = 64; off > 0; off >>= 1) {
        if (j < off) buf[j] = buf[j] + buf[j + off];
        __syncthreads();
    }
    float r = e / buf[0];
    g_St[(size_t)b * 16384 + (size_t)j * 128 + i] = r;   // [b][c][k]
}

// ---------------- kernel 5: out[b,c,n] = sum_k sim[b,k,c]*x[b,k,n], fp16 MMA ----
#define LDA 136
#define LDB 72
#define TN  64
#define NSUB 8

#define ATTN_SMEM 104448

__global__ __launch_bounds__(256, 2) void attn_mma_kernel(const float* __restrict__ x,
                                                          float* __restrict__ out)
{
    extern __shared__ char smraw[];
    __half* Ahi = (__half*)smraw;              // [128 c][LDA k]
    __half* B0  = Ahi + 128 * LDA;             // [128 k][LDB n], double buffered
    __half* B1  = B0 + 128 * LDB;
    float*  Xs  = (float*)(B1 + 128 * LDB);    // staging [128 k][64 n] fp32

    int b    = blockIdx.y;
    int tid  = threadIdx.x;
    int warp = tid >> 5, lane = tid & 31;

    const float* xb = x + (size_t)b * 128 * 65536;
    float*       ob = out + (size_t)b * 128 * 65536;

    {
        int n0 = blockIdx.x * (NSUB * TN);
#pragma unroll
        for (int i = 0; i < 8; ++i) {
            int idx = i * 256 + tid;
            int k = idx >> 4, c4 = idx & 15;
            CP_ASYNC16(smem_u32(Xs + k * TN + c4 * 4),
                       xb + (size_t)k * 65536 + n0 + c4 * 4);
        }
        CP_COMMIT();
    }

    {
        const float* Sp = g_St + (size_t)b * 16384;
#pragma unroll
        for (int i = 0; i < 16; ++i) {
            int idx = i * 256 + tid;
            int c = idx >> 5, k4 = (idx & 31) * 4;
            float4 v = *(const float4*)(Sp + c * 128 + k4);
            __half* ph = Ahi + c * LDA + k4;
            *(__half2*)(ph)     = __floats2half2_rn(v.x, v.y);
            *(__half2*)(ph + 2) = __floats2half2_rn(v.z, v.w);
        }
    }

    int mw = (warp >> 1) * 32;
    int nw = (warp & 1) * 32;
    int r  = lane & 15, q = lane >> 4;

    for (int t = 0; t < NSUB; ++t) {
        __half* Bp = (t & 1) ? B1 : B0;
        int n0 = (blockIdx.x * NSUB + t) * TN;

        CP_WAIT0();
#pragma unroll
        for (int i = 0; i < 8; ++i) {
            int idx = i * 256 + tid;
            int k = idx >> 4, c4 = idx & 15;
            float4 v = *(const float4*)(Xs + k * TN + c4 * 4);
            __half* ph = Bp + k * LDB + c4 * 4;
            *(__half2*)(ph)     = __floats2half2_rn(v.x, v.y);
            *(__half2*)(ph + 2) = __floats2half2_rn(v.z, v.w);
        }

        if (t + 1 < NSUB) {
            int n0n = n0 + TN;
#pragma unroll
            for (int i = 0; i < 8; ++i) {
                int idx = i * 256 + tid;
                int k = idx >> 4, c4 = idx & 15;
                CP_ASYNC16(smem_u32(Xs + k * TN + c4 * 4),
                           xb + (size_t)k * 65536 + n0n + c4 * 4);
            }
            CP_COMMIT();
        }

        __syncthreads();

        float acc[2][4][4];
#pragma unroll
        for (int mf = 0; mf < 2; ++mf)
#pragma unroll
            for (int nf = 0; nf < 4; ++nf)
#pragma unroll
                for (int e = 0; e < 4; ++e) acc[mf][nf][e] = 0.f;

#pragma unroll
        for (int ks = 0; ks < 8; ++ks) {
            int k0 = ks * 16;
            unsigned ah[2][4];
#pragma unroll
            for (int mf = 0; mf < 2; ++mf)
                LDSM_X4(ah[mf], smem_u32(Ahi + (mw + mf * 16 + r) * LDA + k0 + q * 8));
#pragma unroll
            for (int nc = 0; nc < 2; ++nc) {
                unsigned bf[4];
                LDSM_X4_T(bf, smem_u32(Bp + (k0 + r) * LDB + nw + nc * 16 + q * 8));
#pragma unroll
                for (int mf = 0; mf < 2; ++mf) {
#pragma unroll
                    for (int h = 0; h < 2; ++h) {
                        float* C = acc[mf][nc * 2 + h];
                        MMAF16(C, ah[mf], bf[2 * h], bf[2 * h + 1]);
                    }
                }
            }
        }

        int rbase = mw + (lane >> 2);
        int cbase = nw + ((lane & 3) << 1);
#pragma unroll
        for (int mf = 0; mf < 2; ++mf) {
#pragma unroll
            for (int nf = 0; nf < 4; ++nf) {
                float* p0 = ob + (size_t)(rbase + mf * 16) * 65536 + n0 + cbase + nf * 8;
                float* p1 = p0 + 8ull * 65536;
                *(float2*)p0 = make_float2(acc[mf][nf][0], acc[mf][nf][1]);
                *(float2*)p1 = make_float2(acc[mf][nf][2], acc[mf][nf][3]);
            }
        }
    }
}

// ---------------- launch ----------------
extern "C" void kernel_launch(void* const* d_in, const int* in_sizes, int n_in,
                              void* d_out, int out_size)
{
    (void)in_sizes; (void)n_in; (void)out_size;
    const float* x    = (const float*)d_in[0];
    const float* c1w  = (const float*)d_in[1];
    const float* g1   = (const float*)d_in[2];
    const float* b1   = (const float*)d_in[3];
    const float* m1   = (const float*)d_in[4];
    const float* v1   = (const float*)d_in[5];
    const float* a1   = (const float*)d_in[6];
    const float* c2w  = (const float*)d_in[7];
    const float* g2   = (const float*)d_in[8];
    const float* b2   = (const float*)d_in[9];
    const float* m2   = (const float*)d_in[10];
    const float* v2   = (const float*)d_in[11];
    const float* a2   = (const float*)d_in[12];
    float* out = (float*)d_out;

    void* tmp;
    cudaGetSymbolAddress(&tmp, g_p1h);  __half* p1 = (__half*)tmp;
    cudaGetSymbolAddress(&tmp, g_p2h);  __half* p2 = (__half*)tmp;

    cudaFuncSetAttribute(gram_mma_kernel,
                         cudaFuncAttributeMaxDynamicSharedMemorySize, 128 * LDP * 2);
    cudaFuncSetAttribute(attn_mma_kernel,
                         cudaFuncAttributeMaxDynamicSharedMemorySize, ATTN_SMEM);

    dwconv1_kernel<<<dim3(16, 1, 1024), dim3(32, 8)>>>(x, p1, c1w, g1, b1, m1, v1, a1);
    dwconv2_kernel<<<dim3(4, 1, 1024), dim3(16, 16)>>>(p1, p2, c2w, g2, b2, m2, v2, a2);
    gram_mma_kernel<<<dim3(16, 8), 256, 128 * LDP * 2>>>();
    softmax_kernel<<<dim3(128, 8), 128>>>();
    attn_mma_kernel<<<dim3(128, 8), 256, ATTN_SMEM>>>(x, out);
}